// round 2
// baseline (speedup 1.0000x reference)
#include <cuda_runtime.h>
#include <cuda_bf16.h>
#include <math.h>

typedef unsigned long long ull;

#define NPROP   1000
#define FM_C    256
#define FM_HW   10000
#define POOLK   12544      // 49*256
#define HID     1024
#define NCLS    21
#define NFG     20
#define NCAND   20000      // NPROP * NFG
#define MAXDET  100

// ---------------- scratch (device globals; no allocation allowed) -------------
__device__ float  g_fmT[FM_HW * FM_C];          // [hw][c]  10.24MB
__device__ float  g_pooled[NPROP * POOLK];      // [n][cell*256+c] 50.2MB
__device__ float  g_part[2 * NPROP * HID];      // split-K partials 8MB
__device__ float  g_x1[NPROP * HID];
__device__ float  g_x2[NPROP * HID];
__device__ float  g_head[NPROP * 105];          // 21 logits + 84 deltas per row
__device__ float4 g_boxes[NCAND];
__device__ float4 g_boxoff[NCAND];
__device__ float  g_cand[NCAND];

// ---------------- helpers ------------------------------------------------------
__device__ __forceinline__ ull fma2(ull a, ull b, ull c) {
    ull d;
    asm("fma.rn.f32x2 %0, %1, %2, %3;" : "=l"(d) : "l"(a), "l"(b), "l"(c));
    return d;
}
__device__ __forceinline__ ull dup2(float a) {
    ull d;
    asm("mov.b64 %0, {%1, %1};" : "=l"(d) : "f"(a));
    return d;
}
union U64F2 { ull u; float2 f; };

// ---------------- 0: transpose feature map [256,10000] -> [10000,256] ----------
__global__ void transpose_fm(const float* __restrict__ fm) {
    __shared__ float tile[32][33];
    int hw0 = blockIdx.x * 32;
    int c0  = blockIdx.y * 32;
    int tx = threadIdx.x, ty = threadIdx.y;   // 32 x 8
#pragma unroll
    for (int j = 0; j < 32; j += 8) {
        int hw = hw0 + tx;
        float v = (hw < FM_HW) ? fm[(c0 + ty + j) * FM_HW + hw] : 0.f;
        tile[ty + j][tx] = v;
    }
    __syncthreads();
#pragma unroll
    for (int j = 0; j < 32; j += 8) {
        int hw = hw0 + ty + j;
        if (hw < FM_HW) g_fmT[hw * FM_C + c0 + tx] = tile[tx][ty + j];
    }
}

// ---------------- 1: ROI align -------------------------------------------------
// block = 64 threads (4 channels each, float4), one block per ROI
__global__ void roi_align_kernel(const float* __restrict__ rois) {
    int n = blockIdx.x;
    int t = threadIdx.x;      // 0..63
    float4 r = ((const float4*)rois)[n];
    float b0 = r.x * 0.125f - 0.5f;
    float b1 = r.y * 0.125f - 0.5f;
    float b2 = r.z * 0.125f - 0.5f;
    float b3 = r.w * 0.125f - 0.5f;
    float bw = (b2 - b0) / 7.0f;
    float bh = (b3 - b1) / 7.0f;

    __shared__ int   sx0[14], sx1[14], sy0[14], sy1[14];
    __shared__ float swx0[14], swx1[14], swy0[14], swy1[14], svx[14], svy[14];
    if (t < 14) {
        int p = t >> 1, s = t & 1;
        float off = (float)p + ((float)s + 0.5f) * 0.5f;
        // x axis
        float v = b0 + off * bw;
        svx[t] = (v >= -1.0f && v <= 100.0f) ? 1.f : 0.f;
        v = fminf(fmaxf(v, 0.f), 99.f);
        float v0 = floorf(v);
        int i0 = (int)v0;
        sx0[t] = i0; sx1[t] = min(i0 + 1, 99);
        swx1[t] = v - v0; swx0[t] = 1.f - (v - v0);
        // y axis
        v = b1 + off * bh;
        svy[t] = (v >= -1.0f && v <= 100.0f) ? 1.f : 0.f;
        v = fminf(fmaxf(v, 0.f), 99.f);
        v0 = floorf(v);
        i0 = (int)v0;
        sy0[t] = i0; sy1[t] = min(i0 + 1, 99);
        swy1[t] = v - v0; swy0[t] = 1.f - (v - v0);
    }
    __syncthreads();

    const float4* fmT4 = (const float4*)g_fmT;    // (y*100+x)*64 + t
    float4* outp = (float4*)(g_pooled + (size_t)n * POOLK);

    for (int ph = 0; ph < 7; ph++) {
        for (int pw = 0; pw < 7; pw++) {
            float ax = 0.f, ay = 0.f, az = 0.f, aw = 0.f;
#pragma unroll
            for (int sy = 0; sy < 2; sy++) {
                int j = ph * 2 + sy;
                int y0 = sy0[j], y1 = sy1[j];
                float wy0 = swy0[j], wy1 = swy1[j], vy = svy[j];
#pragma unroll
                for (int sx = 0; sx < 2; sx++) {
                    int k = pw * 2 + sx;
                    float m = vy * svx[k];
                    if (m != 0.f) {
                        int x0 = sx0[k], x1 = sx1[k];
                        float w00 = wy0 * swx0[k], w01 = wy0 * swx1[k];
                        float w10 = wy1 * swx0[k], w11 = wy1 * swx1[k];
                        float4 f00 = fmT4[(y0 * 100 + x0) * 64 + t];
                        float4 f01 = fmT4[(y0 * 100 + x1) * 64 + t];
                        float4 f10 = fmT4[(y1 * 100 + x0) * 64 + t];
                        float4 f11 = fmT4[(y1 * 100 + x1) * 64 + t];
                        ax += w00 * f00.x + w01 * f01.x + w10 * f10.x + w11 * f11.x;
                        ay += w00 * f00.y + w01 * f01.y + w10 * f10.y + w11 * f11.y;
                        az += w00 * f00.z + w01 * f01.z + w10 * f10.z + w11 * f11.z;
                        aw += w00 * f00.w + w01 * f01.w + w10 * f10.w + w11 * f11.w;
                    }
                }
            }
            float4 o = make_float4(ax * 0.25f, ay * 0.25f, az * 0.25f, aw * 0.25f);
            outp[(ph * 7 + pw) * 64 + t] = o;
        }
    }
}

// ---------------- 2: SGEMM with packed f32x2 FMA, split-K ----------------------
// C_partial[split][m*1024+n] = A[m, kslice] @ B[kslice, n]
// BM=128 BN=64 BK=16, 128 threads, 8x8 per thread.
#define BM 128
#define BN 64
#define BK 16

__global__ __launch_bounds__(128, 2)
void sgemm_kernel(const float* __restrict__ A, const float* __restrict__ B,
                  float* __restrict__ Cp,
                  int M, int N, int K, int lda, int ldb, int perm) {
    __shared__ float As[2][BK][BM];
    __shared__ float Bs[2][BK][BN];

    int t  = threadIdx.x;
    int tx = t & 7;            // 0..7  (N dir, 8 cols each)
    int ty = t >> 3;           // 0..15 (M dir, 8 rows each)
    int n0 = blockIdx.x * BN;
    int m0 = blockIdx.y * BM;
    int split = blockIdx.z;
    int nsplit = gridDim.z;
    int kLen = K / nsplit;
    int kb0  = split * kLen;
    int nkt  = kLen / BK;

    int m_load = m0 + t;
    bool mok = m_load < M;

    float4 aR[4];
    float4 bR[2];

    auto gload = [&](int kb) {
        const float* Arow = A + (size_t)m_load * lda + kb;
#pragma unroll
        for (int i = 0; i < 4; i++)
            aR[i] = mok ? *(const float4*)(Arow + i * 4) : make_float4(0, 0, 0, 0);
#pragma unroll
        for (int i = 0; i < 2; i++) {
            int id = t + i * 128;
            int krow = id >> 4;
            int col  = (id & 15) * 4;
            int brow = kb + krow;
            if (perm) brow = (brow & 255) * 49 + (brow >> 8);
            bR[i] = *(const float4*)(B + (size_t)brow * ldb + n0 + col);
        }
    };
    auto sstore = [&](int buf) {
#pragma unroll
        for (int i = 0; i < 4; i++) {
            As[buf][i * 4 + 0][t] = aR[i].x;
            As[buf][i * 4 + 1][t] = aR[i].y;
            As[buf][i * 4 + 2][t] = aR[i].z;
            As[buf][i * 4 + 3][t] = aR[i].w;
        }
#pragma unroll
        for (int i = 0; i < 2; i++) {
            int id = t + i * 128;
            int krow = id >> 4;
            int col  = (id & 15) * 4;
            *(float4*)&Bs[buf][krow][col] = bR[i];
        }
    };

    ull acc[8][4];
#pragma unroll
    for (int i = 0; i < 8; i++)
#pragma unroll
        for (int j = 0; j < 4; j++) acc[i][j] = 0ull;

    gload(kb0);
    sstore(0);
    __syncthreads();

    for (int kt = 0; kt < nkt; kt++) {
        if (kt + 1 < nkt) gload(kb0 + (kt + 1) * BK);
        int buf = kt & 1;
#pragma unroll
        for (int k = 0; k < BK; k++) {
            float4 a0 = *(const float4*)&As[buf][k][ty * 8];
            float4 a1 = *(const float4*)&As[buf][k][ty * 8 + 4];
            ull b0 = *(const ull*)&Bs[buf][k][tx * 8];
            ull b1 = *(const ull*)&Bs[buf][k][tx * 8 + 2];
            ull b2 = *(const ull*)&Bs[buf][k][tx * 8 + 4];
            ull b3 = *(const ull*)&Bs[buf][k][tx * 8 + 6];
            ull ax;
            ax = dup2(a0.x); acc[0][0]=fma2(ax,b0,acc[0][0]); acc[0][1]=fma2(ax,b1,acc[0][1]); acc[0][2]=fma2(ax,b2,acc[0][2]); acc[0][3]=fma2(ax,b3,acc[0][3]);
            ax = dup2(a0.y); acc[1][0]=fma2(ax,b0,acc[1][0]); acc[1][1]=fma2(ax,b1,acc[1][1]); acc[1][2]=fma2(ax,b2,acc[1][2]); acc[1][3]=fma2(ax,b3,acc[1][3]);
            ax = dup2(a0.z); acc[2][0]=fma2(ax,b0,acc[2][0]); acc[2][1]=fma2(ax,b1,acc[2][1]); acc[2][2]=fma2(ax,b2,acc[2][2]); acc[2][3]=fma2(ax,b3,acc[2][3]);
            ax = dup2(a0.w); acc[3][0]=fma2(ax,b0,acc[3][0]); acc[3][1]=fma2(ax,b1,acc[3][1]); acc[3][2]=fma2(ax,b2,acc[3][2]); acc[3][3]=fma2(ax,b3,acc[3][3]);
            ax = dup2(a1.x); acc[4][0]=fma2(ax,b0,acc[4][0]); acc[4][1]=fma2(ax,b1,acc[4][1]); acc[4][2]=fma2(ax,b2,acc[4][2]); acc[4][3]=fma2(ax,b3,acc[4][3]);
            ax = dup2(a1.y); acc[5][0]=fma2(ax,b0,acc[5][0]); acc[5][1]=fma2(ax,b1,acc[5][1]); acc[5][2]=fma2(ax,b2,acc[5][2]); acc[5][3]=fma2(ax,b3,acc[5][3]);
            ax = dup2(a1.z); acc[6][0]=fma2(ax,b0,acc[6][0]); acc[6][1]=fma2(ax,b1,acc[6][1]); acc[6][2]=fma2(ax,b2,acc[6][2]); acc[6][3]=fma2(ax,b3,acc[6][3]);
            ax = dup2(a1.w); acc[7][0]=fma2(ax,b0,acc[7][0]); acc[7][1]=fma2(ax,b1,acc[7][1]); acc[7][2]=fma2(ax,b2,acc[7][2]); acc[7][3]=fma2(ax,b3,acc[7][3]);
        }
        if (kt + 1 < nkt) {
            sstore(buf ^ 1);
            __syncthreads();
        }
    }

    float* Cout = Cp + (size_t)split * NPROP * HID;
#pragma unroll
    for (int i = 0; i < 8; i++) {
        int mrow = m0 + ty * 8 + i;
        if (mrow < M) {
            U64F2 u0, u1, u2, u3;
            u0.u = acc[i][0]; u1.u = acc[i][1]; u2.u = acc[i][2]; u3.u = acc[i][3];
            float4 c0 = make_float4(u0.f.x, u0.f.y, u1.f.x, u1.f.y);
            float4 c1 = make_float4(u2.f.x, u2.f.y, u3.f.x, u3.f.y);
            float* row = Cout + (size_t)mrow * HID + n0 + tx * 8;
            *(float4*)(row)     = c0;
            *(float4*)(row + 4) = c1;
        }
    }
}

// sum split-K partials + bias + relu
__global__ void fixup_relu(const float* __restrict__ p, const float* __restrict__ bias,
                           float* __restrict__ out) {
    int i = blockIdx.x * 256 + threadIdx.x;
    if (i < NPROP * HID) {
        float v = p[i] + p[NPROP * HID + i] + bias[i & (HID - 1)];
        out[i] = fmaxf(v, 0.f);
    }
}

// ---------------- 3: heads: x2 @ [wc | wb] + [bc | bb] -------------------------
__global__ void heads_kernel(const float* __restrict__ wc, const float* __restrict__ bc,
                             const float* __restrict__ wb, const float* __restrict__ bb) {
    __shared__ float xs[8 * HID];
    int m0 = blockIdx.x * 8;
    int t = threadIdx.x;    // 128
    const float4* src = (const float4*)(g_x2 + (size_t)m0 * HID);
    float4* dst = (float4*)xs;
    for (int i = t; i < 8 * HID / 4; i += 128) dst[i] = src[i];
    __syncthreads();
    if (t < 105) {
        float acc[8];
#pragma unroll
        for (int r = 0; r < 8; r++) acc[r] = 0.f;
        for (int k = 0; k < HID; k++) {
            float wv = (t < 21) ? wc[k * 21 + t] : wb[k * 84 + (t - 21)];
#pragma unroll
            for (int r = 0; r < 8; r++) acc[r] += xs[r * HID + k] * wv;
        }
        float bv = (t < 21) ? bc[t] : bb[t - 21];
#pragma unroll
        for (int r = 0; r < 8; r++) g_head[(size_t)(m0 + r) * 105 + t] = acc[r] + bv;
    }
}

// ---------------- 4: softmax + decode + candidate setup ------------------------
__global__ void postproc_kernel(const float* __restrict__ rois) {
    int m = blockIdx.x * 128 + threadIdx.x;
    if (m >= NPROP) return;
    const float* h = g_head + (size_t)m * 105;
    float lg[21];
    float mx = -INFINITY;
#pragma unroll
    for (int c = 0; c < 21; c++) { lg[c] = h[c]; mx = fmaxf(mx, lg[c]); }
    float sum = 0.f;
#pragma unroll
    for (int c = 0; c < 21; c++) { lg[c] = expf(lg[c] - mx); sum += lg[c]; }
    float inv = 1.0f / sum;

    float4 r = ((const float4*)rois)[m];
    float w  = r.z - r.x;
    float hh = r.w - r.y;
    float cx = r.x + 0.5f * w;
    float cy = r.y + 0.5f * hh;

#pragma unroll
    for (int c = 1; c < 21; c++) {
        float sc = lg[c] * inv;
        float dx = h[21 + (c - 1) * 0 + c * 4 + 0 - 4 + 4];  // placeholder avoided below
        // deltas for class c live at head cols 21 + c*4 .. 21 + c*4 + 3
        dx       = h[21 + c * 4 + 0];
        float dy = h[21 + c * 4 + 1];
        float dw = h[21 + c * 4 + 2];
        float dh = h[21 + c * 4 + 3];
        float pcx = dx * w + cx;
        float pcy = dy * hh + cy;
        float pw  = expf(dw) * w;
        float ph2 = expf(dh) * hh;
        float x1 = pcx - 0.5f * pw,  y1 = pcy - 0.5f * ph2;
        float x2 = pcx + 0.5f * pw,  y2 = pcy + 0.5f * ph2;
        int i = m * NFG + (c - 1);
        g_boxes[i]  = make_float4(x1, y1, x2, y2);
        float off = (float)c * 10000.0f;
        g_boxoff[i] = make_float4(x1 + off, y1 + off, x2 + off, y2 + off);
        g_cand[i] = (sc > 0.05f) ? sc : -1.0f;
    }
}

// ---------------- 5: sequential NMS (single block) -----------------------------
__global__ void nms_kernel(float* __restrict__ out) {
    extern __shared__ float s[];    // NCAND scores
    __shared__ float rv[32];
    __shared__ int   ri[32];
    __shared__ float4 pboxS;
    __shared__ int   keepI[MAXDET];
    __shared__ float keepV[MAXDET];
    int t = threadIdx.x;   // 1024
    for (int i = t; i < NCAND; i += 1024) s[i] = g_cand[i];
    __syncthreads();

    float4 pb = make_float4(0, 0, 0, 0);
    float parea = 0.f;
    bool have = false;

    for (int it = 0; it < MAXDET; it++) {
        float bv = -INFINITY;
        int bi = 0x7fffffff;
#pragma unroll
        for (int w = 0; w < 20; w++) {
            int i = t + (w << 10);
            if (i < NCAND) {
                float v = s[i];
                if (have && v > -INFINITY) {
                    float4 b = g_boxoff[i];
                    float ix1 = fmaxf(pb.x, b.x), iy1 = fmaxf(pb.y, b.y);
                    float ix2 = fminf(pb.z, b.z), iy2 = fminf(pb.w, b.w);
                    float inter = fmaxf(ix2 - ix1, 0.f) * fmaxf(iy2 - iy1, 0.f);
                    float A = (b.z - b.x) * (b.w - b.y);
                    float iou = inter / (parea + A - inter + 1e-9f);
                    if (iou > 0.5f) { v = -INFINITY; s[i] = v; }
                }
                if (v > bv || (v == bv && i < bi)) { bv = v; bi = i; }
            }
        }
#pragma unroll
        for (int o = 16; o; o >>= 1) {
            float ov = __shfl_down_sync(0xffffffffu, bv, o);
            int   oi = __shfl_down_sync(0xffffffffu, bi, o);
            if (ov > bv || (ov == bv && oi < bi)) { bv = ov; bi = oi; }
        }
        if ((t & 31) == 0) { rv[t >> 5] = bv; ri[t >> 5] = bi; }
        __syncthreads();
        if (t < 32) {
            bv = rv[t]; bi = ri[t];
#pragma unroll
            for (int o = 16; o; o >>= 1) {
                float ov = __shfl_down_sync(0xffffffffu, bv, o);
                int   oi = __shfl_down_sync(0xffffffffu, bi, o);
                if (ov > bv || (ov == bv && oi < bi)) { bv = ov; bi = oi; }
            }
            if (t == 0) {
                keepI[it] = bi;
                keepV[it] = bv;
                pboxS = g_boxoff[bi];
            }
        }
        __syncthreads();
        pb = pboxS;
        parea = (pb.z - pb.x) * (pb.w - pb.y);
        have = true;
    }
    __syncthreads();

    // output layout: [0:400) boxes, [400:500) scores, [500:600) labels(as float)
    if (t < MAXDET) {
        int ki = keepI[t];
        float ks = keepV[t];
        bool valid = ks > 0.05f;
        float4 b = g_boxes[ki];
        float vm = valid ? 1.f : 0.f;
        out[t * 4 + 0] = b.x * vm;
        out[t * 4 + 1] = b.y * vm;
        out[t * 4 + 2] = b.z * vm;
        out[t * 4 + 3] = b.w * vm;
        out[400 + t] = valid ? ks : 0.f;
        out[500 + t] = valid ? (float)((ki % NFG) + 1) : 0.f;
    }
}

__global__ void zero_out(float* out, int n) {
    int i = blockIdx.x * 256 + threadIdx.x;
    if (i < n) out[i] = 0.f;
}

// ---------------- launcher ------------------------------------------------------
extern "C" void kernel_launch(void* const* d_in, const int* in_sizes, int n_in,
                              void* d_out, int out_size) {
    const float* fm  = (const float*)d_in[0];
    const float* pr  = (const float*)d_in[1];
    const float* w1  = (const float*)d_in[2];
    const float* b1  = (const float*)d_in[3];
    const float* w2  = (const float*)d_in[4];
    const float* b2  = (const float*)d_in[5];
    const float* wc  = (const float*)d_in[6];
    const float* bc  = (const float*)d_in[7];
    const float* wb  = (const float*)d_in[8];
    const float* bb  = (const float*)d_in[9];
    float* out = (float*)d_out;

    float *pooled, *part, *x1, *x2;
    cudaGetSymbolAddress((void**)&pooled, g_pooled);
    cudaGetSymbolAddress((void**)&part,   g_part);
    cudaGetSymbolAddress((void**)&x1,     g_x1);
    cudaGetSymbolAddress((void**)&x2,     g_x2);

    zero_out<<<(out_size + 255) / 256, 256>>>(out, out_size);
    transpose_fm<<<dim3(313, 8), dim3(32, 8)>>>(fm);
    roi_align_kernel<<<NPROP, 64>>>(pr);

    // GEMM1: pooled[1000,12544] @ perm(w1)[12544,1024], split-K=2
    sgemm_kernel<<<dim3(HID / BN, (NPROP + BM - 1) / BM, 2), 128>>>(
        pooled, w1, part, NPROP, HID, POOLK, POOLK, HID, 1);
    fixup_relu<<<(NPROP * HID + 255) / 256, 256>>>(part, b1, x1);

    // GEMM2: x1[1000,1024] @ w2[1024,1024], split-K=2
    sgemm_kernel<<<dim3(HID / BN, (NPROP + BM - 1) / BM, 2), 128>>>(
        x1, w2, part, NPROP, HID, HID, HID, HID, 0);
    fixup_relu<<<(NPROP * HID + 255) / 256, 256>>>(part, b2, x2);

    heads_kernel<<<NPROP / 8, 128>>>(wc, bc, wb, bb);
    postproc_kernel<<<(NPROP + 127) / 128, 128>>>(pr);

    cudaFuncSetAttribute(nms_kernel, cudaFuncAttributeMaxDynamicSharedMemorySize,
                         NCAND * sizeof(float));
    nms_kernel<<<1, 1024, NCAND * sizeof(float)>>>(out);
}

// round 4
// speedup vs baseline: 1.6518x; 1.6518x over previous
#include <cuda_runtime.h>
#include <cuda_bf16.h>
#include <math.h>
#include <stdint.h>

#define NPROP 1000
#define MPAD  1024
#define FM_HW 10000
#define K1    12544
#define HID   1024
#define NCAND 20000
#define MAXDET 100
#define KC    32

typedef __nv_bfloat16 bf;

// ---------------- scratch ----------------
__device__ float g_fmT[FM_HW * 256];
__device__ float g_pooled[NPROP * K1];
__device__ bf g_A0[MPAD*K1], g_A1[MPAD*K1], g_A2[MPAD*K1];
__device__ bf g_W10[HID*K1], g_W11[HID*K1], g_W12[HID*K1];
__device__ bf g_X1a[MPAD*HID], g_X1b[MPAD*HID], g_X1c[MPAD*HID];
__device__ bf g_W20[HID*HID], g_W21[HID*HID], g_W22[HID*HID];
__device__ bf g_X2a[MPAD*HID], g_X2b[MPAD*HID], g_X2c[MPAD*HID];
__device__ bf g_WH0[128*HID], g_WH1[128*HID], g_WH2[128*HID];
__device__ float g_bh[128];
__device__ float g_part[2 * MPAD * HID];
__device__ float g_head[NPROP * 105];
__device__ float4 g_boxes[NCAND], g_boxoff[NCAND];
__device__ float g_cand[NCAND];
__device__ float g_cscore[NCAND];
__device__ int   g_cidx[NCAND];
__device__ float4 g_cboxes[NCAND], g_cboxoff[NCAND];
__device__ int   g_ccount;

// ---------------- PTX helpers ----------------
__device__ __forceinline__ uint32_t s2u(const void* p){
    uint32_t a; asm("{ .reg .u64 t; cvta.to.shared.u64 t, %1; cvt.u32.u64 %0, t; }":"=r"(a):"l"(p)); return a;
}
__device__ __forceinline__ void cpa16(uint32_t s, const void* g){
    asm volatile("cp.async.cg.shared.global [%0], [%1], 16;"::"r"(s),"l"(g):"memory");
}
__device__ __forceinline__ void ldsm4(uint32_t* r, uint32_t addr){
    asm volatile("ldmatrix.sync.aligned.m8n8.x4.shared.b16 {%0,%1,%2,%3}, [%4];"
        :"=r"(r[0]),"=r"(r[1]),"=r"(r[2]),"=r"(r[3]):"r"(addr));
}
__device__ __forceinline__ void mma16816(float* d, const uint32_t* a, const uint32_t* b){
    asm volatile("mma.sync.aligned.m16n8k16.row.col.f32.bf16.bf16.f32 "
        "{%0,%1,%2,%3}, {%4,%5,%6,%7}, {%8,%9}, {%0,%1,%2,%3};"
        :"+f"(d[0]),"+f"(d[1]),"+f"(d[2]),"+f"(d[3])
        :"r"(a[0]),"r"(a[1]),"r"(a[2]),"r"(a[3]),"r"(b[0]),"r"(b[1]));
}
__device__ __forceinline__ void split3(float v, bf& b0, bf& b1, bf& b2){
    b0 = __float2bfloat16(v);
    float r = v - __bfloat162float(b0);
    b1 = __float2bfloat16(r);
    r -= __bfloat162float(b1);
    b2 = __float2bfloat16(r);
}

// ---------------- transpose FM ----------------
__global__ void transpose_fm(const float* __restrict__ fm){
    __shared__ float tl[32][33];
    int hw0 = blockIdx.x*32, c0 = blockIdx.y*32, tx = threadIdx.x, ty = threadIdx.y;
#pragma unroll
    for (int j = 0; j < 32; j += 8){
        int hw = hw0 + tx;
        tl[ty+j][tx] = (hw < FM_HW) ? fm[(c0+ty+j)*FM_HW + hw] : 0.f;
    }
    __syncthreads();
#pragma unroll
    for (int j = 0; j < 32; j += 8){
        int hw = hw0 + ty + j;
        if (hw < FM_HW) g_fmT[hw*256 + c0 + tx] = tl[tx][ty+j];
    }
}

// ---------------- ROI align ----------------
__global__ void roi_align_kernel(const float* __restrict__ rois){
    int n = blockIdx.x, t = threadIdx.x;
    int tc = t & 63, cg = t >> 6;
    float4 r = ((const float4*)rois)[n];
    float b0 = r.x*0.125f - 0.5f, b1 = r.y*0.125f - 0.5f;
    float bw = (r.z*0.125f - 0.5f - b0) / 7.0f, bh = (r.w*0.125f - 0.5f - b1) / 7.0f;
    __shared__ int sx0[14], sx1[14], sy0[14], sy1[14];
    __shared__ float swx0[14], swx1[14], swy0[14], swy1[14], svx[14], svy[14];
    if (t < 14){
        int p = t >> 1, s = t & 1;
        float off = (float)p + ((float)s + 0.5f)*0.5f;
        float v = b0 + off*bw;
        svx[t] = (v >= -1.f && v <= 100.f) ? 1.f : 0.f;
        v = fminf(fmaxf(v, 0.f), 99.f);
        float v0 = floorf(v); int i0 = (int)v0;
        sx0[t] = i0; sx1[t] = min(i0+1, 99); swx1[t] = v - v0; swx0[t] = 1.f - (v - v0);
        v = b1 + off*bh;
        svy[t] = (v >= -1.f && v <= 100.f) ? 1.f : 0.f;
        v = fminf(fmaxf(v, 0.f), 99.f);
        v0 = floorf(v); i0 = (int)v0;
        sy0[t] = i0; sy1[t] = min(i0+1, 99); swy1[t] = v - v0; swy0[t] = 1.f - (v - v0);
    }
    __syncthreads();
    const float4* fmT4 = (const float4*)g_fmT;
    float4* outp = (float4*)(g_pooled + (size_t)n*K1);
    for (int cell = cg; cell < 49; cell += 4){
        int ph = cell / 7, pw = cell - ph*7;
        float ax = 0, ay = 0, az = 0, aw = 0;
#pragma unroll
        for (int sy = 0; sy < 2; sy++){
            int j = ph*2 + sy;
            int y0 = sy0[j], y1 = sy1[j];
            float wy0 = swy0[j], wy1 = swy1[j], vy = svy[j];
#pragma unroll
            for (int sx = 0; sx < 2; sx++){
                int k = pw*2 + sx;
                if (vy * svx[k] != 0.f){
                    int x0 = sx0[k], x1 = sx1[k];
                    float w00 = wy0*swx0[k], w01 = wy0*swx1[k], w10 = wy1*swx0[k], w11 = wy1*swx1[k];
                    float4 f00 = fmT4[(y0*100+x0)*64+tc], f01 = fmT4[(y0*100+x1)*64+tc];
                    float4 f10 = fmT4[(y1*100+x0)*64+tc], f11 = fmT4[(y1*100+x1)*64+tc];
                    ax += w00*f00.x + w01*f01.x + w10*f10.x + w11*f11.x;
                    ay += w00*f00.y + w01*f01.y + w10*f10.y + w11*f11.y;
                    az += w00*f00.z + w01*f01.z + w10*f10.z + w11*f11.z;
                    aw += w00*f00.w + w01*f01.w + w10*f10.w + w11*f11.w;
                }
            }
        }
        outp[cell*64 + tc] = make_float4(ax*0.25f, ay*0.25f, az*0.25f, aw*0.25f);
    }
}

// ---------------- pooled [cell*256+c] -> A splits at [c*49+cell] ----------------
__global__ void conv_pooled(){
    extern __shared__ float sm[];
    int n = blockIdx.x, t = threadIdx.x;
    if (n < NPROP){
        const float* s = g_pooled + (size_t)n*K1;
        for (int k = t; k < K1; k += 256) sm[k + (k >> 8)] = s[k];
    }
    __syncthreads();
    size_t b = (size_t)n*K1;
    for (int j = t; j < K1; j += 256){
        float v = 0.f;
        if (n < NPROP){
            int c = j / 49, cell = j - c*49;
            int k = cell*256 + c;
            v = sm[k + (k >> 8)];
        }
        bf h0, h1, h2; split3(v, h0, h1, h2);
        g_A0[b+j] = h0; g_A1[b+j] = h1; g_A2[b+j] = h2;
    }
}

// ---------------- transpose + split weights: in[R][C] -> out[C][R] ----------------
__global__ void conv_T(const float* __restrict__ in, int R, int C,
                       bf* __restrict__ o0, bf* __restrict__ o1, bf* __restrict__ o2){
    __shared__ float tl[32][33];
    int r0 = blockIdx.y*32, c0 = blockIdx.x*32, tx = threadIdx.x, ty = threadIdx.y;
#pragma unroll
    for (int j = 0; j < 32; j += 8)
        tl[ty+j][tx] = in[(size_t)(r0+ty+j)*C + c0 + tx];
    __syncthreads();
#pragma unroll
    for (int j = 0; j < 32; j += 8){
        float v = tl[tx][ty+j];
        size_t o = (size_t)(c0+ty+j)*R + r0 + tx;
        bf h0, h1, h2; split3(v, h0, h1, h2);
        o0[o] = h0; o1[o] = h1; o2[o] = h2;
    }
}

// ---------------- heads weights -> [128][1024] padded ----------------
__global__ void conv_heads(const float* __restrict__ wc, const float* __restrict__ bc,
                           const float* __restrict__ wb, const float* __restrict__ bb){
    int h = blockIdx.x;
    for (int k = threadIdx.x; k < HID; k += 256){
        float v = (h < 21) ? wc[k*21 + h] : ((h < 105) ? wb[k*84 + (h-21)] : 0.f);
        bf h0, h1, h2; split3(v, h0, h1, h2);
        size_t o = (size_t)h*HID + k;
        g_WH0[o] = h0; g_WH1[o] = h1; g_WH2[o] = h2;
    }
    if (threadIdx.x == 0)
        g_bh[h] = (h < 21) ? bc[h] : ((h < 105) ? bb[h-21] : 0.f);
}

// ---------------- mma.sync bf16 GEMM (triple split, 6 terms) ----------------
// D[m][n] = sum_k A[m][k]*B[n][k]. 128x128 tile, KC=32, double buffer cp.async.
// mode 0: write fp32 partial to Cp[z][m][n]; mode 1: Oh[m*105+n]=D+bias.
// smem: 6 tiles x [128 rows][80B] per buffer = 61440B x2
#define GSMEM (2*6*128*80)

__global__ __launch_bounds__(256, 1)
void gemm_mma(const bf* __restrict__ A0, const bf* __restrict__ A1, const bf* __restrict__ A2,
              const bf* __restrict__ B0, const bf* __restrict__ B1, const bf* __restrict__ B2,
              const float* __restrict__ bias, int K, int mode,
              float* __restrict__ Cp, float* __restrict__ Oh){
    extern __shared__ char smraw[];
    uint32_t sbase = s2u(smraw);
    int t = threadIdx.x, lane = t & 31, wid = t >> 5;
    int wm = wid & 1, wn = wid >> 1;            // 2 x 4 warp grid
    int m0 = blockIdx.y * 128, n0 = blockIdx.x * 128;
    int z = blockIdx.z, nz = gridDim.z;
    int kslice = K / nz, kbase = z * kslice, nch = kslice / KC;

    const bf* srcs[6] = {A0 + (size_t)m0*K, A1 + (size_t)m0*K, A2 + (size_t)m0*K,
                         B0 + (size_t)n0*K, B1 + (size_t)n0*K, B2 + (size_t)n0*K};

    float acc[4][4][4];
#pragma unroll
    for (int i = 0; i < 4; i++)
#pragma unroll
        for (int j = 0; j < 4; j++)
#pragma unroll
            for (int k = 0; k < 4; k++) acc[i][j][k] = 0.f;

    // prefetch chunk 0
    {
        uint32_t stb = sbase;
#pragma unroll
        for (int i = 0; i < 12; i++){
            int v = t + i*256;
            int tile = v >> 9, idx = v & 511;
            int row = idx >> 2, grp = idx & 3;
            cpa16(stb + tile*10240 + row*80 + grp*16,
                  srcs[tile] + (size_t)row*K + kbase + grp*8);
        }
        asm volatile("cp.async.commit_group;":::"memory");
    }

    for (int c = 0; c < nch; c++){
        int buf = c & 1;
        if (c + 1 < nch){
            uint32_t stb = sbase + (buf^1)*61440;
            int ko = kbase + (c+1)*KC;
#pragma unroll
            for (int i = 0; i < 12; i++){
                int v = t + i*256;
                int tile = v >> 9, idx = v & 511;
                int row = idx >> 2, grp = idx & 3;
                cpa16(stb + tile*10240 + row*80 + grp*16,
                      srcs[tile] + (size_t)row*K + ko + grp*8);
            }
            asm volatile("cp.async.commit_group;":::"memory");
            asm volatile("cp.async.wait_group 1;":::"memory");
        } else {
            asm volatile("cp.async.wait_group 0;":::"memory");
        }
        __syncthreads();
        uint32_t stb = sbase + buf*61440;
        uint32_t lsel = (lane & 15)*80 + (lane >> 4)*16;
#pragma unroll
        for (int ks = 0; ks < 2; ks++){
            uint32_t koff = ks*32;
            uint32_t a[3][4][4], b[3][4][2];
#pragma unroll
            for (int s = 0; s < 3; s++){
#pragma unroll
                for (int i = 0; i < 4; i++)
                    ldsm4(a[s][i], stb + s*10240 + (wm*64 + i*16)*80 + lsel + koff);
#pragma unroll
                for (int jj = 0; jj < 2; jj++){
                    uint32_t r[4];
                    ldsm4(r, stb + (3+s)*10240 + (wn*32 + jj*16)*80 + lsel + koff);
                    b[s][jj*2  ][0] = r[0]; b[s][jj*2  ][1] = r[2];
                    b[s][jj*2+1][0] = r[1]; b[s][jj*2+1][1] = r[3];
                }
            }
            const int ta[6] = {0,0,1,1,0,2}, tb[6] = {0,1,0,1,2,0};
#pragma unroll
            for (int e = 0; e < 6; e++)
#pragma unroll
                for (int i = 0; i < 4; i++)
#pragma unroll
                    for (int j = 0; j < 4; j++)
                        mma16816(acc[i][j], a[ta[e]][i], b[tb[e]][j]);
        }
        __syncthreads();
    }

    if (mode == 0){
        float* outp = Cp + (size_t)z * MPAD * HID;
#pragma unroll
        for (int i = 0; i < 4; i++){
            int mr = m0 + wm*64 + i*16 + (lane >> 2);
#pragma unroll
            for (int j = 0; j < 4; j++){
                int nc = n0 + wn*32 + j*8 + (lane & 3)*2;
                *(float2*)(outp + (size_t)mr*HID + nc) = make_float2(acc[i][j][0], acc[i][j][1]);
                *(float2*)(outp + (size_t)(mr+8)*HID + nc) = make_float2(acc[i][j][2], acc[i][j][3]);
            }
        }
    } else {
#pragma unroll
        for (int i = 0; i < 4; i++){
#pragma unroll
            for (int j = 0; j < 4; j++){
                int nc = n0 + wn*32 + j*8 + (lane & 3)*2;
#pragma unroll
                for (int h = 0; h < 2; h++){
                    int m = m0 + wm*64 + i*16 + (lane >> 2) + h*8;
                    if (m < NPROP){
                        if (nc < 105)   Oh[(size_t)m*105 + nc]   = acc[i][j][h*2]   + bias[nc];
                        if (nc+1 < 105) Oh[(size_t)m*105 + nc+1] = acc[i][j][h*2+1] + bias[nc+1];
                    }
                }
            }
        }
    }
}

// ---------------- sum split-K partials + bias + relu + split3 ----------------
__global__ void fixup_split(const float* __restrict__ p, const float* __restrict__ bias,
                            bf* __restrict__ o0, bf* __restrict__ o1, bf* __restrict__ o2){
    int i = blockIdx.x*256 + threadIdx.x;
    float v = fmaxf(p[i] + p[MPAD*HID + i] + bias[i & (HID-1)], 0.f);
    bf h0, h1, h2; split3(v, h0, h1, h2);
    o0[i] = h0; o1[i] = h1; o2[i] = h2;
}

// ---------------- softmax + decode ----------------
__global__ void postproc_kernel(const float* __restrict__ rois){
    int m = blockIdx.x*128 + threadIdx.x;
    if (m >= NPROP) return;
    const float* h = g_head + (size_t)m*105;
    float lg[21], mx = -INFINITY;
#pragma unroll
    for (int c = 0; c < 21; c++){ lg[c] = h[c]; mx = fmaxf(mx, lg[c]); }
    float sum = 0.f;
#pragma unroll
    for (int c = 0; c < 21; c++){ lg[c] = expf(lg[c] - mx); sum += lg[c]; }
    float inv = 1.0f / sum;
    float4 r = ((const float4*)rois)[m];
    float w = r.z - r.x, hh = r.w - r.y;
    float cx = r.x + 0.5f*w, cy = r.y + 0.5f*hh;
#pragma unroll
    for (int c = 1; c < 21; c++){
        float sc = lg[c]*inv;
        float dx = h[21 + c*4 + 0], dy = h[21 + c*4 + 1];
        float dw = h[21 + c*4 + 2], dh = h[21 + c*4 + 3];
        float pcx = dx*w + cx, pcy = dy*hh + cy;
        float pw = expf(dw)*w, ph2 = expf(dh)*hh;
        float x1 = pcx - 0.5f*pw, y1 = pcy - 0.5f*ph2;
        float x2 = pcx + 0.5f*pw, y2 = pcy + 0.5f*ph2;
        int i = m*20 + (c - 1);
        g_boxes[i] = make_float4(x1, y1, x2, y2);
        float off = (float)c * 10000.0f;
        g_boxoff[i] = make_float4(x1 + off, y1 + off, x2 + off, y2 + off);
        g_cand[i] = sc;
    }
}

// ---------------- stable compaction (score > 0.05) ----------------
__global__ void compact_kernel(){
    __shared__ int woff[33];
    __shared__ int sbase;
    int t = threadIdx.x, w = t >> 5, l = t & 31;
    if (t == 0) sbase = 0;
    __syncthreads();
    for (int r = 0; r < NCAND; r += 1024){
        int i = r + t;
        float v = (i < NCAND) ? g_cand[i] : 0.f;
        bool p = (i < NCAND) && (v > 0.05f);
        unsigned bal = __ballot_sync(~0u, p);
        int pre = __popc(bal & ((1u << l) - 1));
        if (l == 0) woff[w] = __popc(bal);
        __syncthreads();
        if (t == 0){
            int s = sbase;
            for (int k = 0; k < 32; k++){ int x = woff[k]; woff[k] = s; s += x; }
            woff[32] = s;
            sbase = s;
        }
        __syncthreads();
        if (p){
            int d = woff[w] + pre;
            g_cscore[d] = v; g_cidx[d] = i;
            g_cboxoff[d] = g_boxoff[i]; g_cboxes[d] = g_boxes[i];
        }
        __syncthreads();
    }
    if (t == 0) g_ccount = sbase;
}

// ---------------- NMS on compacted set + early exit ----------------
__global__ void nms_kernel(float* __restrict__ out){
    extern __shared__ float s[];
    __shared__ float rv[32]; __shared__ int ri[32];
    __shared__ float4 pbS; __shared__ int s_stop, s_nd;
    __shared__ int keepI[MAXDET]; __shared__ float keepV[MAXDET];
    int t = threadIdx.x;
    int C = g_ccount;
    for (int i = t; i < C; i += 1024) s[i] = g_cscore[i];
    if (t == 0){ s_stop = 0; s_nd = 0; }
    __syncthreads();
    float4 pb = make_float4(0,0,0,0); float parea = 0.f; bool have = false;
    for (int it = 0; it < MAXDET; it++){
        float bv = -INFINITY; int bi = 1 << 30;
        for (int i = t; i < C; i += 1024){
            float v = s[i];
            if (have && v > -INFINITY){
                float4 b = g_cboxoff[i];
                float ix1 = fmaxf(pb.x, b.x), iy1 = fmaxf(pb.y, b.y);
                float ix2 = fminf(pb.z, b.z), iy2 = fminf(pb.w, b.w);
                float inter = fmaxf(ix2 - ix1, 0.f) * fmaxf(iy2 - iy1, 0.f);
                float A = (b.z - b.x) * (b.w - b.y);
                if (inter / (parea + A - inter + 1e-9f) > 0.5f){ v = -INFINITY; s[i] = v; }
            }
            if (v > bv || (v == bv && i < bi)){ bv = v; bi = i; }
        }
#pragma unroll
        for (int o = 16; o; o >>= 1){
            float ov = __shfl_down_sync(~0u, bv, o);
            int oi = __shfl_down_sync(~0u, bi, o);
            if (ov > bv || (ov == bv && oi < bi)){ bv = ov; bi = oi; }
        }
        if ((t & 31) == 0){ rv[t >> 5] = bv; ri[t >> 5] = bi; }
        __syncthreads();
        if (t < 32){
            bv = rv[t]; bi = ri[t];
#pragma unroll
            for (int o = 16; o; o >>= 1){
                float ov = __shfl_down_sync(~0u, bv, o);
                int oi = __shfl_down_sync(~0u, bi, o);
                if (ov > bv || (ov == bv && oi < bi)){ bv = ov; bi = oi; }
            }
            if (t == 0){
                if (bv > 0.05f){
                    keepI[s_nd] = bi; keepV[s_nd] = bv; s_nd++;
                    pbS = g_cboxoff[bi];
                } else s_stop = 1;
            }
        }
        __syncthreads();
        if (s_stop) break;
        pb = pbS; parea = (pb.z - pb.x) * (pb.w - pb.y); have = true;
        __syncthreads();
    }
    __syncthreads();
    if (t < s_nd){
        int ki = keepI[t];
        float4 b = g_cboxes[ki];
        out[t*4+0] = b.x; out[t*4+1] = b.y; out[t*4+2] = b.z; out[t*4+3] = b.w;
        out[400 + t] = keepV[t];
        out[500 + t] = (float)((g_cidx[ki] % 20) + 1);
    }
}

__global__ void zero_out(float* out, int n){
    int i = blockIdx.x*256 + threadIdx.x;
    if (i < n) out[i] = 0.f;
}

// ---------------- launcher ----------------
extern "C" void kernel_launch(void* const* d_in, const int* in_sizes, int n_in,
                              void* d_out, int out_size){
    const float* fm = (const float*)d_in[0];
    const float* pr = (const float*)d_in[1];
    const float* w1 = (const float*)d_in[2];
    const float* b1 = (const float*)d_in[3];
    const float* w2 = (const float*)d_in[4];
    const float* b2 = (const float*)d_in[5];
    const float* wc = (const float*)d_in[6];
    const float* bc = (const float*)d_in[7];
    const float* wb = (const float*)d_in[8];
    const float* bb = (const float*)d_in[9];
    float* out = (float*)d_out;

    bf *A0,*A1,*A2,*W10,*W11,*W12,*X1a,*X1b,*X1c,*W20,*W21,*W22,*X2a,*X2b,*X2c,*WH0,*WH1,*WH2;
    float *bh, *head, *part;
    cudaGetSymbolAddress((void**)&A0, g_A0);  cudaGetSymbolAddress((void**)&A1, g_A1);
    cudaGetSymbolAddress((void**)&A2, g_A2);
    cudaGetSymbolAddress((void**)&W10, g_W10); cudaGetSymbolAddress((void**)&W11, g_W11);
    cudaGetSymbolAddress((void**)&W12, g_W12);
    cudaGetSymbolAddress((void**)&X1a, g_X1a); cudaGetSymbolAddress((void**)&X1b, g_X1b);
    cudaGetSymbolAddress((void**)&X1c, g_X1c);
    cudaGetSymbolAddress((void**)&W20, g_W20); cudaGetSymbolAddress((void**)&W21, g_W21);
    cudaGetSymbolAddress((void**)&W22, g_W22);
    cudaGetSymbolAddress((void**)&X2a, g_X2a); cudaGetSymbolAddress((void**)&X2b, g_X2b);
    cudaGetSymbolAddress((void**)&X2c, g_X2c);
    cudaGetSymbolAddress((void**)&WH0, g_WH0); cudaGetSymbolAddress((void**)&WH1, g_WH1);
    cudaGetSymbolAddress((void**)&WH2, g_WH2);
    cudaGetSymbolAddress((void**)&bh, g_bh);   cudaGetSymbolAddress((void**)&head, g_head);
    cudaGetSymbolAddress((void**)&part, g_part);

    cudaFuncSetAttribute(gemm_mma, cudaFuncAttributeMaxDynamicSharedMemorySize, GSMEM);
    cudaFuncSetAttribute(conv_pooled, cudaFuncAttributeMaxDynamicSharedMemorySize, 50372);
    cudaFuncSetAttribute(nms_kernel, cudaFuncAttributeMaxDynamicSharedMemorySize, NCAND*4);

    zero_out<<<(out_size + 255) / 256, 256>>>(out, out_size);
    transpose_fm<<<dim3(313, 8), dim3(32, 8)>>>(fm);
    roi_align_kernel<<<NPROP, 256>>>(pr);
    conv_pooled<<<MPAD, 256, 50372>>>();
    conv_T<<<dim3(32, 392), dim3(32, 8)>>>(w1, K1, HID, W10, W11, W12);
    conv_T<<<dim3(32, 32), dim3(32, 8)>>>(w2, HID, HID, W20, W21, W22);
    conv_heads<<<128, 256>>>(wc, bc, wb, bb);

    // FC1: [1024,12544] @ [12544,1024], split-K=2
    gemm_mma<<<dim3(8, 8, 2), 256, GSMEM>>>(A0, A1, A2, W10, W11, W12, nullptr, K1, 0, part, nullptr);
    fixup_split<<<MPAD*HID/256, 256>>>(part, b1, X1a, X1b, X1c);
    // FC2
    gemm_mma<<<dim3(8, 8, 2), 256, GSMEM>>>(X1a, X1b, X1c, W20, W21, W22, nullptr, HID, 0, part, nullptr);
    fixup_split<<<MPAD*HID/256, 256>>>(part, b2, X2a, X2b, X2c);
    // heads
    gemm_mma<<<dim3(1, 8, 1), 256, GSMEM>>>(X2a, X2b, X2c, WH0, WH1, WH2, bh, HID, 1, nullptr, head);

    postproc_kernel<<<8, 128>>>(pr);
    compact_kernel<<<1, 1024>>>();
    nms_kernel<<<1, 1024, NCAND*4>>>(out);
}

// round 5
// speedup vs baseline: 2.0242x; 1.2254x over previous
#include <cuda_runtime.h>
#include <cuda_bf16.h>
#include <math.h>
#include <stdint.h>

#define NPROP 1000
#define MPAD  1024
#define FM_HW 10000
#define K1    12544
#define HID   1024
#define NCAND 20000
#define MAXDET 100
#define KC    32

typedef __nv_bfloat16 bf;

// ---------------- scratch ----------------
__device__ float g_fmT[FM_HW * 256];
__device__ float g_pooled[NPROP * K1];
__device__ bf g_A0[MPAD*K1], g_A1[MPAD*K1];
__device__ bf g_W10[HID*K1], g_W11[HID*K1];
__device__ bf g_X1a[MPAD*HID], g_X1b[MPAD*HID];
__device__ bf g_W20[HID*HID], g_W21[HID*HID];
__device__ bf g_X2a[MPAD*HID], g_X2b[MPAD*HID];
__device__ bf g_WH0[128*HID], g_WH1[128*HID];
__device__ float g_bh[128];
__device__ float g_part[2 * MPAD * HID];
__device__ float g_head[NPROP * 105];
__device__ float4 g_boxes[NCAND], g_boxoff[NCAND];
__device__ float g_cand[NCAND];
__device__ float g_cscore[NCAND];
__device__ int   g_cidx[NCAND];
__device__ float4 g_cboxes[NCAND], g_cboxoff[NCAND];
__device__ int   g_ccount;

// ---------------- PTX helpers ----------------
__device__ __forceinline__ uint32_t s2u(const void* p){
    uint32_t a; asm("{ .reg .u64 t; cvta.to.shared.u64 t, %1; cvt.u32.u64 %0, t; }":"=r"(a):"l"(p)); return a;
}
__device__ __forceinline__ void cpa16(uint32_t s, const void* g){
    asm volatile("cp.async.cg.shared.global [%0], [%1], 16;"::"r"(s),"l"(g):"memory");
}
__device__ __forceinline__ void ldsm4(uint32_t* r, uint32_t addr){
    asm volatile("ldmatrix.sync.aligned.m8n8.x4.shared.b16 {%0,%1,%2,%3}, [%4];"
        :"=r"(r[0]),"=r"(r[1]),"=r"(r[2]),"=r"(r[3]):"r"(addr));
}
__device__ __forceinline__ void mma16816(float* d, const uint32_t* a, const uint32_t* b){
    asm volatile("mma.sync.aligned.m16n8k16.row.col.f32.bf16.bf16.f32 "
        "{%0,%1,%2,%3}, {%4,%5,%6,%7}, {%8,%9}, {%0,%1,%2,%3};"
        :"+f"(d[0]),"+f"(d[1]),"+f"(d[2]),"+f"(d[3])
        :"r"(a[0]),"r"(a[1]),"r"(a[2]),"r"(a[3]),"r"(b[0]),"r"(b[1]));
}
__device__ __forceinline__ void split2(float v, bf& b0, bf& b1){
    b0 = __float2bfloat16(v);
    b1 = __float2bfloat16(v - __bfloat162float(b0));
}

// ---------------- transpose FM ----------------
__global__ void transpose_fm(const float* __restrict__ fm){
    __shared__ float tl[32][33];
    int hw0 = blockIdx.x*32, c0 = blockIdx.y*32, tx = threadIdx.x, ty = threadIdx.y;
#pragma unroll
    for (int j = 0; j < 32; j += 8){
        int hw = hw0 + tx;
        tl[ty+j][tx] = (hw < FM_HW) ? fm[(c0+ty+j)*FM_HW + hw] : 0.f;
    }
    __syncthreads();
#pragma unroll
    for (int j = 0; j < 32; j += 8){
        int hw = hw0 + ty + j;
        if (hw < FM_HW) g_fmT[hw*256 + c0 + tx] = tl[tx][ty+j];
    }
}

// ---------------- ROI align ----------------
__global__ void roi_align_kernel(const float* __restrict__ rois){
    int n = blockIdx.x, t = threadIdx.x;
    int tc = t & 63, cg = t >> 6;
    float4 r = ((const float4*)rois)[n];
    float b0 = r.x*0.125f - 0.5f, b1 = r.y*0.125f - 0.5f;
    float bw = (r.z*0.125f - 0.5f - b0) / 7.0f, bh = (r.w*0.125f - 0.5f - b1) / 7.0f;
    __shared__ int sx0[14], sx1[14], sy0[14], sy1[14];
    __shared__ float swx0[14], swx1[14], swy0[14], swy1[14], svx[14], svy[14];
    if (t < 14){
        int p = t >> 1, s = t & 1;
        float off = (float)p + ((float)s + 0.5f)*0.5f;
        float v = b0 + off*bw;
        svx[t] = (v >= -1.f && v <= 100.f) ? 1.f : 0.f;
        v = fminf(fmaxf(v, 0.f), 99.f);
        float v0 = floorf(v); int i0 = (int)v0;
        sx0[t] = i0; sx1[t] = min(i0+1, 99); swx1[t] = v - v0; swx0[t] = 1.f - (v - v0);
        v = b1 + off*bh;
        svy[t] = (v >= -1.f && v <= 100.f) ? 1.f : 0.f;
        v = fminf(fmaxf(v, 0.f), 99.f);
        v0 = floorf(v); i0 = (int)v0;
        sy0[t] = i0; sy1[t] = min(i0+1, 99); swy1[t] = v - v0; swy0[t] = 1.f - (v - v0);
    }
    __syncthreads();
    const float4* fmT4 = (const float4*)g_fmT;
    float4* outp = (float4*)(g_pooled + (size_t)n*K1);
    for (int cell = cg; cell < 49; cell += 4){
        int ph = cell / 7, pw = cell - ph*7;
        float ax = 0, ay = 0, az = 0, aw = 0;
#pragma unroll
        for (int sy = 0; sy < 2; sy++){
            int j = ph*2 + sy;
            int y0 = sy0[j], y1 = sy1[j];
            float wy0 = swy0[j], wy1 = swy1[j], vy = svy[j];
#pragma unroll
            for (int sx = 0; sx < 2; sx++){
                int k = pw*2 + sx;
                if (vy * svx[k] != 0.f){
                    int x0 = sx0[k], x1 = sx1[k];
                    float w00 = wy0*swx0[k], w01 = wy0*swx1[k], w10 = wy1*swx0[k], w11 = wy1*swx1[k];
                    float4 f00 = fmT4[(y0*100+x0)*64+tc], f01 = fmT4[(y0*100+x1)*64+tc];
                    float4 f10 = fmT4[(y1*100+x0)*64+tc], f11 = fmT4[(y1*100+x1)*64+tc];
                    ax += w00*f00.x + w01*f01.x + w10*f10.x + w11*f11.x;
                    ay += w00*f00.y + w01*f01.y + w10*f10.y + w11*f11.y;
                    az += w00*f00.z + w01*f01.z + w10*f10.z + w11*f11.z;
                    aw += w00*f00.w + w01*f01.w + w10*f10.w + w11*f11.w;
                }
            }
        }
        outp[cell*64 + tc] = make_float4(ax*0.25f, ay*0.25f, az*0.25f, aw*0.25f);
    }
}

// ---------------- pooled [cell*256+c] -> A splits at [c*49+cell] ----------------
__global__ void conv_pooled(){
    extern __shared__ float sm[];
    int n = blockIdx.x, t = threadIdx.x;
    if (n < NPROP){
        const float* s = g_pooled + (size_t)n*K1;
        for (int k = t; k < K1; k += 256) sm[k + (k >> 8)] = s[k];
    }
    __syncthreads();
    size_t b = (size_t)n*K1;
    for (int j = t; j < K1; j += 256){
        float v = 0.f;
        if (n < NPROP){
            int c = j / 49, cell = j - c*49;
            int k = cell*256 + c;
            v = sm[k + (k >> 8)];
        }
        bf h0, h1; split2(v, h0, h1);
        g_A0[b+j] = h0; g_A1[b+j] = h1;
    }
}

// ---------------- transpose + split weights: in[R][C] -> out[C][R] ----------------
__global__ void conv_T(const float* __restrict__ in, int R, int C,
                       bf* __restrict__ o0, bf* __restrict__ o1){
    __shared__ float tl[32][33];
    int r0 = blockIdx.y*32, c0 = blockIdx.x*32, tx = threadIdx.x, ty = threadIdx.y;
#pragma unroll
    for (int j = 0; j < 32; j += 8)
        tl[ty+j][tx] = in[(size_t)(r0+ty+j)*C + c0 + tx];
    __syncthreads();
#pragma unroll
    for (int j = 0; j < 32; j += 8){
        float v = tl[tx][ty+j];
        size_t o = (size_t)(c0+ty+j)*R + r0 + tx;
        bf h0, h1; split2(v, h0, h1);
        o0[o] = h0; o1[o] = h1;
    }
}

// ---------------- heads weights -> [128][1024] padded ----------------
__global__ void conv_heads(const float* __restrict__ wc, const float* __restrict__ bc,
                           const float* __restrict__ wb, const float* __restrict__ bb){
    int h = blockIdx.x;
    for (int k = threadIdx.x; k < HID; k += 256){
        float v = (h < 21) ? wc[k*21 + h] : ((h < 105) ? wb[k*84 + (h-21)] : 0.f);
        bf h0, h1; split2(v, h0, h1);
        size_t o = (size_t)h*HID + k;
        g_WH0[o] = h0; g_WH1[o] = h1;
    }
    if (threadIdx.x == 0)
        g_bh[h] = (h < 21) ? bc[h] : ((h < 105) ? bb[h-21] : 0.f);
}

// ---------------- mma.sync bf16 GEMM (split-2, 4 terms) ----------------
// D[m][n] = sum_k A[m][k]*B[n][k]. BM=128, BN=64, KC=32, double buffer.
// smem/buf: A0,A1: 128x80B each; B0,B1: 64x80B each = 30720B; x2 = 61440B
#define GSMEM 61440

__global__ __launch_bounds__(256, 2)
void gemm_mma(const bf* __restrict__ A0, const bf* __restrict__ A1,
              const bf* __restrict__ B0, const bf* __restrict__ B1,
              const float* __restrict__ bias, int K, int mode,
              float* __restrict__ Cp, float* __restrict__ Oh){
    extern __shared__ char smraw[];
    uint32_t sbase = s2u(smraw);
    int t = threadIdx.x, lane = t & 31, wid = t >> 5;
    int wm = wid & 1, wn = wid >> 1;            // 2 x 4 warps: 64 m-rows x 16 n-cols each
    int m0 = blockIdx.y * 128, n0 = blockIdx.x * 64;
    int z = blockIdx.z, nz = gridDim.z;
    int kslice = K / nz, kbase = z * kslice, nch = kslice / KC;

    const bf* srcA[2] = {A0 + (size_t)m0*K, A1 + (size_t)m0*K};
    const bf* srcB[2] = {B0 + (size_t)n0*K, B1 + (size_t)n0*K};

    float acc[4][2][4];
#pragma unroll
    for (int i = 0; i < 4; i++)
#pragma unroll
        for (int j = 0; j < 2; j++)
#pragma unroll
            for (int k = 0; k < 4; k++) acc[i][j][k] = 0.f;

    auto loadChunk = [&](uint32_t stb, int ko){
#pragma unroll
        for (int i = 0; i < 6; i++){
            int v = t + i*256;
            if (v < 1024){
                int tile = v >> 9, idx = v & 511;
                int row = idx >> 2, grp = idx & 3;
                cpa16(stb + tile*10240 + row*80 + grp*16,
                      srcA[tile] + (size_t)row*K + ko + grp*8);
            } else {
                int u = v - 1024;
                int tile = u >> 8, idx = u & 255;
                int row = idx >> 2, grp = idx & 3;
                cpa16(stb + 20480 + tile*5120 + row*80 + grp*16,
                      srcB[tile] + (size_t)row*K + ko + grp*8);
            }
        }
        asm volatile("cp.async.commit_group;":::"memory");
    };

    loadChunk(sbase, kbase);

    uint32_t lsel = (lane & 15)*80 + (lane >> 4)*16;
    for (int c = 0; c < nch; c++){
        int buf = c & 1;
        if (c + 1 < nch){
            loadChunk(sbase + (buf^1)*30720, kbase + (c+1)*KC);
            asm volatile("cp.async.wait_group 1;":::"memory");
        } else {
            asm volatile("cp.async.wait_group 0;":::"memory");
        }
        __syncthreads();
        uint32_t stb = sbase + buf*30720;
#pragma unroll
        for (int ks = 0; ks < 2; ks++){
            uint32_t koff = ks*32;
            uint32_t a[2][4][4], b[2][2][2];
#pragma unroll
            for (int s = 0; s < 2; s++){
#pragma unroll
                for (int i = 0; i < 4; i++)
                    ldsm4(a[s][i], stb + s*10240 + (wm*64 + i*16)*80 + lsel + koff);
                uint32_t r[4];
                ldsm4(r, stb + 20480 + s*5120 + (wn*16)*80 + lsel + koff);
                b[s][0][0] = r[0]; b[s][0][1] = r[2];
                b[s][1][0] = r[1]; b[s][1][1] = r[3];
            }
            const int ta[4] = {0,0,1,1}, tb[4] = {0,1,0,1};
#pragma unroll
            for (int e = 0; e < 4; e++)
#pragma unroll
                for (int i = 0; i < 4; i++)
#pragma unroll
                    for (int j = 0; j < 2; j++)
                        mma16816(acc[i][j], a[ta[e]][i], b[tb[e]][j]);
        }
        __syncthreads();
    }

    if (mode == 0){
        float* outp = Cp + (size_t)z * MPAD * HID;
#pragma unroll
        for (int i = 0; i < 4; i++){
            int mr = m0 + wm*64 + i*16 + (lane >> 2);
#pragma unroll
            for (int j = 0; j < 2; j++){
                int nc = n0 + wn*16 + j*8 + (lane & 3)*2;
                *(float2*)(outp + (size_t)mr*HID + nc) = make_float2(acc[i][j][0], acc[i][j][1]);
                *(float2*)(outp + (size_t)(mr+8)*HID + nc) = make_float2(acc[i][j][2], acc[i][j][3]);
            }
        }
    } else {
#pragma unroll
        for (int i = 0; i < 4; i++){
#pragma unroll
            for (int j = 0; j < 2; j++){
                int nc = n0 + wn*16 + j*8 + (lane & 3)*2;
#pragma unroll
                for (int h = 0; h < 2; h++){
                    int m = m0 + wm*64 + i*16 + (lane >> 2) + h*8;
                    if (m < NPROP){
                        if (nc < 105)   Oh[(size_t)m*105 + nc]   = acc[i][j][h*2]   + bias[nc];
                        if (nc+1 < 105) Oh[(size_t)m*105 + nc+1] = acc[i][j][h*2+1] + bias[nc+1];
                    }
                }
            }
        }
    }
}

// ---------------- sum split-K partials + bias + relu + split2 ----------------
__global__ void fixup_split(const float* __restrict__ p, const float* __restrict__ bias,
                            bf* __restrict__ o0, bf* __restrict__ o1){
    int i = blockIdx.x*256 + threadIdx.x;
    float v = fmaxf(p[i] + p[MPAD*HID + i] + bias[i & (HID-1)], 0.f);
    bf h0, h1; split2(v, h0, h1);
    o0[i] = h0; o1[i] = h1;
}

// ---------------- softmax + decode ----------------
__global__ void postproc_kernel(const float* __restrict__ rois){
    int m = blockIdx.x*128 + threadIdx.x;
    if (m >= NPROP) return;
    const float* h = g_head + (size_t)m*105;
    float lg[21], mx = -INFINITY;
#pragma unroll
    for (int c = 0; c < 21; c++){ lg[c] = h[c]; mx = fmaxf(mx, lg[c]); }
    float sum = 0.f;
#pragma unroll
    for (int c = 0; c < 21; c++){ lg[c] = expf(lg[c] - mx); sum += lg[c]; }
    float inv = 1.0f / sum;
    float4 r = ((const float4*)rois)[m];
    float w = r.z - r.x, hh = r.w - r.y;
    float cx = r.x + 0.5f*w, cy = r.y + 0.5f*hh;
#pragma unroll
    for (int c = 1; c < 21; c++){
        float sc = lg[c]*inv;
        float dx = h[21 + c*4 + 0], dy = h[21 + c*4 + 1];
        float dw = h[21 + c*4 + 2], dh = h[21 + c*4 + 3];
        float pcx = dx*w + cx, pcy = dy*hh + cy;
        float pw = expf(dw)*w, ph2 = expf(dh)*hh;
        float x1 = pcx - 0.5f*pw, y1 = pcy - 0.5f*ph2;
        float x2 = pcx + 0.5f*pw, y2 = pcy + 0.5f*ph2;
        int i = m*20 + (c - 1);
        g_boxes[i] = make_float4(x1, y1, x2, y2);
        float off = (float)c * 10000.0f;
        g_boxoff[i] = make_float4(x1 + off, y1 + off, x2 + off, y2 + off);
        g_cand[i] = sc;
    }
}

// ---------------- stable compaction (score > 0.05) ----------------
__global__ void compact_kernel(){
    __shared__ int woff[33];
    __shared__ int sbase;
    int t = threadIdx.x, w = t >> 5, l = t & 31;
    if (t == 0) sbase = 0;
    __syncthreads();
    for (int r = 0; r < NCAND; r += 1024){
        int i = r + t;
        float v = (i < NCAND) ? g_cand[i] : 0.f;
        bool p = (i < NCAND) && (v > 0.05f);
        unsigned bal = __ballot_sync(~0u, p);
        int pre = __popc(bal & ((1u << l) - 1));
        if (l == 0) woff[w] = __popc(bal);
        __syncthreads();
        if (t == 0){
            int s = sbase;
            for (int k = 0; k < 32; k++){ int x = woff[k]; woff[k] = s; s += x; }
            woff[32] = s;
            sbase = s;
        }
        __syncthreads();
        if (p){
            int d = woff[w] + pre;
            g_cscore[d] = v; g_cidx[d] = i;
            g_cboxoff[d] = g_boxoff[i]; g_cboxes[d] = g_boxes[i];
        }
        __syncthreads();
    }
    if (t == 0) g_ccount = sbase;
}

// ---------------- NMS on compacted set + early exit ----------------
__global__ void nms_kernel(float* __restrict__ out){
    extern __shared__ float s[];
    __shared__ float rv[32]; __shared__ int ri[32];
    __shared__ float4 pbS; __shared__ int s_stop, s_nd;
    __shared__ int keepI[MAXDET]; __shared__ float keepV[MAXDET];
    int t = threadIdx.x;
    int C = g_ccount;
    for (int i = t; i < C; i += 1024) s[i] = g_cscore[i];
    if (t == 0){ s_stop = 0; s_nd = 0; }
    __syncthreads();
    float4 pb = make_float4(0,0,0,0); float parea = 0.f; bool have = false;
    for (int it = 0; it < MAXDET; it++){
        float bv = -INFINITY; int bi = 1 << 30;
        for (int i = t; i < C; i += 1024){
            float v = s[i];
            if (have && v > -INFINITY){
                float4 b = g_cboxoff[i];
                float ix1 = fmaxf(pb.x, b.x), iy1 = fmaxf(pb.y, b.y);
                float ix2 = fminf(pb.z, b.z), iy2 = fminf(pb.w, b.w);
                float inter = fmaxf(ix2 - ix1, 0.f) * fmaxf(iy2 - iy1, 0.f);
                float A = (b.z - b.x) * (b.w - b.y);
                if (inter / (parea + A - inter + 1e-9f) > 0.5f){ v = -INFINITY; s[i] = v; }
            }
            if (v > bv || (v == bv && i < bi)){ bv = v; bi = i; }
        }
#pragma unroll
        for (int o = 16; o; o >>= 1){
            float ov = __shfl_down_sync(~0u, bv, o);
            int oi = __shfl_down_sync(~0u, bi, o);
            if (ov > bv || (ov == bv && oi < bi)){ bv = ov; bi = oi; }
        }
        if ((t & 31) == 0){ rv[t >> 5] = bv; ri[t >> 5] = bi; }
        __syncthreads();
        if (t < 32){
            bv = rv[t]; bi = ri[t];
#pragma unroll
            for (int o = 16; o; o >>= 1){
                float ov = __shfl_down_sync(~0u, bv, o);
                int oi = __shfl_down_sync(~0u, bi, o);
                if (ov > bv || (ov == bv && oi < bi)){ bv = ov; bi = oi; }
            }
            if (t == 0){
                if (bv > 0.05f){
                    keepI[s_nd] = bi; keepV[s_nd] = bv; s_nd++;
                    pbS = g_cboxoff[bi];
                } else s_stop = 1;
            }
        }
        __syncthreads();
        if (s_stop) break;
        pb = pbS; parea = (pb.z - pb.x) * (pb.w - pb.y); have = true;
        __syncthreads();
    }
    __syncthreads();
    if (t < s_nd){
        int ki = keepI[t];
        float4 b = g_cboxes[ki];
        out[t*4+0] = b.x; out[t*4+1] = b.y; out[t*4+2] = b.z; out[t*4+3] = b.w;
        out[400 + t] = keepV[t];
        out[500 + t] = (float)((g_cidx[ki] % 20) + 1);
    }
}

__global__ void zero_out(float* out, int n){
    int i = blockIdx.x*256 + threadIdx.x;
    if (i < n) out[i] = 0.f;
}

// ---------------- launcher ----------------
extern "C" void kernel_launch(void* const* d_in, const int* in_sizes, int n_in,
                              void* d_out, int out_size){
    const float* fm = (const float*)d_in[0];
    const float* pr = (const float*)d_in[1];
    const float* w1 = (const float*)d_in[2];
    const float* b1 = (const float*)d_in[3];
    const float* w2 = (const float*)d_in[4];
    const float* b2 = (const float*)d_in[5];
    const float* wc = (const float*)d_in[6];
    const float* bc = (const float*)d_in[7];
    const float* wb = (const float*)d_in[8];
    const float* bb = (const float*)d_in[9];
    float* out = (float*)d_out;

    bf *A0,*A1,*W10,*W11,*X1a,*X1b,*W20,*W21,*X2a,*X2b,*WH0,*WH1;
    float *bh, *head, *part;
    cudaGetSymbolAddress((void**)&A0, g_A0);   cudaGetSymbolAddress((void**)&A1, g_A1);
    cudaGetSymbolAddress((void**)&W10, g_W10); cudaGetSymbolAddress((void**)&W11, g_W11);
    cudaGetSymbolAddress((void**)&X1a, g_X1a); cudaGetSymbolAddress((void**)&X1b, g_X1b);
    cudaGetSymbolAddress((void**)&W20, g_W20); cudaGetSymbolAddress((void**)&W21, g_W21);
    cudaGetSymbolAddress((void**)&X2a, g_X2a); cudaGetSymbolAddress((void**)&X2b, g_X2b);
    cudaGetSymbolAddress((void**)&WH0, g_WH0); cudaGetSymbolAddress((void**)&WH1, g_WH1);
    cudaGetSymbolAddress((void**)&bh, g_bh);   cudaGetSymbolAddress((void**)&head, g_head);
    cudaGetSymbolAddress((void**)&part, g_part);

    cudaFuncSetAttribute(gemm_mma, cudaFuncAttributeMaxDynamicSharedMemorySize, GSMEM);
    cudaFuncSetAttribute(conv_pooled, cudaFuncAttributeMaxDynamicSharedMemorySize, 50372);
    cudaFuncSetAttribute(nms_kernel, cudaFuncAttributeMaxDynamicSharedMemorySize, NCAND*4);

    zero_out<<<(out_size + 255) / 256, 256>>>(out, out_size);
    transpose_fm<<<dim3(313, 8), dim3(32, 8)>>>(fm);
    roi_align_kernel<<<NPROP, 256>>>(pr);
    conv_pooled<<<MPAD, 256, 50372>>>();
    conv_T<<<dim3(32, 392), dim3(32, 8)>>>(w1, K1, HID, W10, W11);
    conv_T<<<dim3(32, 32), dim3(32, 8)>>>(w2, HID, HID, W20, W21);
    conv_heads<<<128, 256>>>(wc, bc, wb, bb);

    // FC1: [1024,12544] @ [12544,1024], split-K=2
    gemm_mma<<<dim3(16, 8, 2), 256, GSMEM>>>(A0, A1, W10, W11, nullptr, K1, 0, part, nullptr);
    fixup_split<<<MPAD*HID/256, 256>>>(part, b1, X1a, X1b);
    // FC2
    gemm_mma<<<dim3(16, 8, 2), 256, GSMEM>>>(X1a, X1b, W20, W21, nullptr, HID, 0, part, nullptr);
    fixup_split<<<MPAD*HID/256, 256>>>(part, b2, X2a, X2b);
    // heads: N=128 padded
    gemm_mma<<<dim3(2, 8, 1), 256, GSMEM>>>(X2a, X2b, WH0, WH1, bh, HID, 1, nullptr, head);

    postproc_kernel<<<8, 128>>>(pr);
    compact_kernel<<<1, 1024>>>();
    nms_kernel<<<1, 1024, NCAND*4>>>(out);
}

// round 6
// speedup vs baseline: 2.1935x; 1.0836x over previous
#include <cuda_runtime.h>
#include <cuda_bf16.h>
#include <math.h>
#include <stdint.h>

#define NPROP 1000
#define MPAD  1024
#define FM_HW 10000
#define K1    12544
#define HID   1024
#define NCAND 20000
#define MAXDET 100
#define KC    32

typedef __nv_bfloat16 bf;

// ---------------- scratch ----------------
__device__ float g_fmT[FM_HW * 256];
__device__ float g_pooled[NPROP * K1];
__device__ bf g_A0[MPAD*K1], g_A1[MPAD*K1];
__device__ bf g_W10[HID*K1], g_W11[HID*K1];
__device__ bf g_X1a[MPAD*HID], g_X1b[MPAD*HID];
__device__ bf g_W20[HID*HID], g_W21[HID*HID];
__device__ bf g_X2a[MPAD*HID], g_X2b[MPAD*HID];
__device__ bf g_WH0[128*HID], g_WH1[128*HID];
__device__ float g_bh[128];
__device__ float g_part[2 * MPAD * HID];
__device__ float g_head[NPROP * 105];
__device__ float4 g_boxes[NCAND], g_boxoff[NCAND];
__device__ float g_cand[NCAND];
__device__ float g_cscore[NCAND];
__device__ int   g_cidx[NCAND];
__device__ float4 g_cboxes[NCAND], g_cboxoff[NCAND];
__device__ int   g_ccount;

// ---------------- PTX helpers ----------------
__device__ __forceinline__ uint32_t s2u(const void* p){
    uint32_t a; asm("{ .reg .u64 t; cvta.to.shared.u64 t, %1; cvt.u32.u64 %0, t; }":"=r"(a):"l"(p)); return a;
}
__device__ __forceinline__ void cpa16(uint32_t s, const void* g){
    asm volatile("cp.async.cg.shared.global [%0], [%1], 16;"::"r"(s),"l"(g):"memory");
}
__device__ __forceinline__ void ldsm4(uint32_t* r, uint32_t addr){
    asm volatile("ldmatrix.sync.aligned.m8n8.x4.shared.b16 {%0,%1,%2,%3}, [%4];"
        :"=r"(r[0]),"=r"(r[1]),"=r"(r[2]),"=r"(r[3]):"r"(addr));
}
__device__ __forceinline__ void mma16816(float* d, const uint32_t* a, const uint32_t* b){
    asm volatile("mma.sync.aligned.m16n8k16.row.col.f32.bf16.bf16.f32 "
        "{%0,%1,%2,%3}, {%4,%5,%6,%7}, {%8,%9}, {%0,%1,%2,%3};"
        :"+f"(d[0]),"+f"(d[1]),"+f"(d[2]),"+f"(d[3])
        :"r"(a[0]),"r"(a[1]),"r"(a[2]),"r"(a[3]),"r"(b[0]),"r"(b[1]));
}
__device__ __forceinline__ void split2(float v, bf& b0, bf& b1){
    b0 = __float2bfloat16(v);
    b1 = __float2bfloat16(v - __bfloat162float(b0));
}

// ---------------- transpose FM ----------------
__global__ void transpose_fm(const float* __restrict__ fm){
    __shared__ float tl[32][33];
    int hw0 = blockIdx.x*32, c0 = blockIdx.y*32, tx = threadIdx.x, ty = threadIdx.y;
#pragma unroll
    for (int j = 0; j < 32; j += 8){
        int hw = hw0 + tx;
        tl[ty+j][tx] = (hw < FM_HW) ? fm[(c0+ty+j)*FM_HW + hw] : 0.f;
    }
    __syncthreads();
#pragma unroll
    for (int j = 0; j < 32; j += 8){
        int hw = hw0 + ty + j;
        if (hw < FM_HW) g_fmT[hw*256 + c0 + tx] = tl[tx][ty+j];
    }
}

// ---------------- ROI align ----------------
__global__ void roi_align_kernel(const float* __restrict__ rois){
    int n = blockIdx.x, t = threadIdx.x;
    int tc = t & 63, cg = t >> 6;
    float4 r = ((const float4*)rois)[n];
    float b0 = r.x*0.125f - 0.5f, b1 = r.y*0.125f - 0.5f;
    float bw = (r.z*0.125f - 0.5f - b0) / 7.0f, bh = (r.w*0.125f - 0.5f - b1) / 7.0f;
    __shared__ int sx0[14], sx1[14], sy0[14], sy1[14];
    __shared__ float swx0[14], swx1[14], swy0[14], swy1[14], svx[14], svy[14];
    if (t < 14){
        int p = t >> 1, s = t & 1;
        float off = (float)p + ((float)s + 0.5f)*0.5f;
        float v = b0 + off*bw;
        svx[t] = (v >= -1.f && v <= 100.f) ? 1.f : 0.f;
        v = fminf(fmaxf(v, 0.f), 99.f);
        float v0 = floorf(v); int i0 = (int)v0;
        sx0[t] = i0; sx1[t] = min(i0+1, 99); swx1[t] = v - v0; swx0[t] = 1.f - (v - v0);
        v = b1 + off*bh;
        svy[t] = (v >= -1.f && v <= 100.f) ? 1.f : 0.f;
        v = fminf(fmaxf(v, 0.f), 99.f);
        v0 = floorf(v); i0 = (int)v0;
        sy0[t] = i0; sy1[t] = min(i0+1, 99); swy1[t] = v - v0; swy0[t] = 1.f - (v - v0);
    }
    __syncthreads();
    const float4* fmT4 = (const float4*)g_fmT;
    float4* outp = (float4*)(g_pooled + (size_t)n*K1);
    for (int cell = cg; cell < 49; cell += 4){
        int ph = cell / 7, pw = cell - ph*7;
        float ax = 0, ay = 0, az = 0, aw = 0;
#pragma unroll
        for (int sy = 0; sy < 2; sy++){
            int j = ph*2 + sy;
            int y0 = sy0[j], y1 = sy1[j];
            float wy0 = swy0[j], wy1 = swy1[j], vy = svy[j];
#pragma unroll
            for (int sx = 0; sx < 2; sx++){
                int k = pw*2 + sx;
                if (vy * svx[k] != 0.f){
                    int x0 = sx0[k], x1 = sx1[k];
                    float w00 = wy0*swx0[k], w01 = wy0*swx1[k], w10 = wy1*swx0[k], w11 = wy1*swx1[k];
                    float4 f00 = fmT4[(y0*100+x0)*64+tc], f01 = fmT4[(y0*100+x1)*64+tc];
                    float4 f10 = fmT4[(y1*100+x0)*64+tc], f11 = fmT4[(y1*100+x1)*64+tc];
                    ax += w00*f00.x + w01*f01.x + w10*f10.x + w11*f11.x;
                    ay += w00*f00.y + w01*f01.y + w10*f10.y + w11*f11.y;
                    az += w00*f00.z + w01*f01.z + w10*f10.z + w11*f11.z;
                    aw += w00*f00.w + w01*f01.w + w10*f10.w + w11*f11.w;
                }
            }
        }
        outp[cell*64 + tc] = make_float4(ax*0.25f, ay*0.25f, az*0.25f, aw*0.25f);
    }
}

// ---------------- pooled [cell*256+c] -> A splits at [c*49+cell] ----------------
__global__ void conv_pooled(){
    extern __shared__ float sm[];
    int n = blockIdx.x, t = threadIdx.x;
    if (n < NPROP){
        const float* s = g_pooled + (size_t)n*K1;
        for (int k = t; k < K1; k += 256) sm[k + (k >> 8)] = s[k];
    }
    __syncthreads();
    size_t b = (size_t)n*K1;
    for (int j = t; j < K1; j += 256){
        float v = 0.f;
        if (n < NPROP){
            int c = j / 49, cell = j - c*49;
            int k = cell*256 + c;
            v = sm[k + (k >> 8)];
        }
        bf h0, h1; split2(v, h0, h1);
        g_A0[b+j] = h0; g_A1[b+j] = h1;
    }
}

// ---------------- transpose + split weights: in[R][C] -> out[C][R] ----------------
__global__ void conv_T(const float* __restrict__ in, int R, int C,
                       bf* __restrict__ o0, bf* __restrict__ o1){
    __shared__ float tl[32][33];
    int r0 = blockIdx.y*32, c0 = blockIdx.x*32, tx = threadIdx.x, ty = threadIdx.y;
#pragma unroll
    for (int j = 0; j < 32; j += 8)
        tl[ty+j][tx] = in[(size_t)(r0+ty+j)*C + c0 + tx];
    __syncthreads();
#pragma unroll
    for (int j = 0; j < 32; j += 8){
        float v = tl[tx][ty+j];
        size_t o = (size_t)(c0+ty+j)*R + r0 + tx;
        bf h0, h1; split2(v, h0, h1);
        o0[o] = h0; o1[o] = h1;
    }
}

// ---------------- heads weights -> [128][1024] padded ----------------
__global__ void conv_heads(const float* __restrict__ wc, const float* __restrict__ bc,
                           const float* __restrict__ wb, const float* __restrict__ bb){
    int h = blockIdx.x;
    for (int k = threadIdx.x; k < HID; k += 256){
        float v = (h < 21) ? wc[k*21 + h] : ((h < 105) ? wb[k*84 + (h-21)] : 0.f);
        bf h0, h1; split2(v, h0, h1);
        size_t o = (size_t)h*HID + k;
        g_WH0[o] = h0; g_WH1[o] = h1;
    }
    if (threadIdx.x == 0)
        g_bh[h] = (h < 21) ? bc[h] : ((h < 105) ? bb[h-21] : 0.f);
}

// ---------------- mma.sync bf16 GEMM (split-2, 3 terms), BM=128 BN=128 ----------
// 512 threads, 16 warps in 2(m) x 8(n); each warp: 64 m x 16 n.
// smem/buf: A0,A1,B0,B1 each 128x80B = 10240 -> 40960; double buffered 81920.
#define GSMEM 81920

__global__ __launch_bounds__(512, 1)
void gemm_mma(const bf* __restrict__ A0, const bf* __restrict__ A1,
              const bf* __restrict__ B0, const bf* __restrict__ B1,
              const float* __restrict__ bias, int K, int mode,
              float* __restrict__ Cp, float* __restrict__ Oh){
    extern __shared__ char smraw[];
    uint32_t sbase = s2u(smraw);
    int t = threadIdx.x, lane = t & 31, wid = t >> 5;
    int wm = wid & 1, wn = wid >> 1;            // 2 x 8
    int m0 = blockIdx.y * 128, n0 = blockIdx.x * 128;
    int z = blockIdx.z, nz = gridDim.z;
    int kslice = K / nz, kbase = z * kslice, nch = kslice / KC;

    const bf* src[4] = {A0 + (size_t)m0*K, A1 + (size_t)m0*K,
                        B0 + (size_t)n0*K, B1 + (size_t)n0*K};

    float acc[4][2][4];
#pragma unroll
    for (int i = 0; i < 4; i++)
#pragma unroll
        for (int j = 0; j < 2; j++)
#pragma unroll
            for (int k = 0; k < 4; k++) acc[i][j][k] = 0.f;

    auto loadChunk = [&](uint32_t stb, int ko){
#pragma unroll
        for (int i = 0; i < 4; i++){
            int v = t + i*512;
            int tile = v >> 9, idx = v & 511;
            int row = idx >> 2, grp = idx & 3;
            cpa16(stb + tile*10240 + row*80 + grp*16,
                  src[tile] + (size_t)row*K + ko + grp*8);
        }
        asm volatile("cp.async.commit_group;":::"memory");
    };

    loadChunk(sbase, kbase);

    uint32_t lsel = (lane & 15)*80 + (lane >> 4)*16;
    for (int c = 0; c < nch; c++){
        int buf = c & 1;
        if (c + 1 < nch){
            loadChunk(sbase + (buf^1)*40960, kbase + (c+1)*KC);
            asm volatile("cp.async.wait_group 1;":::"memory");
        } else {
            asm volatile("cp.async.wait_group 0;":::"memory");
        }
        __syncthreads();
        uint32_t stb = sbase + buf*40960;
#pragma unroll
        for (int ks = 0; ks < 2; ks++){
            uint32_t koff = ks*32;
            uint32_t a[2][4][4], b[2][2][2];
#pragma unroll
            for (int s = 0; s < 2; s++){
#pragma unroll
                for (int i = 0; i < 4; i++)
                    ldsm4(a[s][i], stb + s*10240 + (wm*64 + i*16)*80 + lsel + koff);
                uint32_t r[4];
                ldsm4(r, stb + 20480 + s*10240 + (wn*16)*80 + lsel + koff);
                b[s][0][0] = r[0]; b[s][0][1] = r[2];
                b[s][1][0] = r[1]; b[s][1][1] = r[3];
            }
            // 3 terms: a0*b0, a0*b1, a1*b0
            const int ta[3] = {0,0,1}, tb[3] = {0,1,0};
#pragma unroll
            for (int e = 0; e < 3; e++)
#pragma unroll
                for (int i = 0; i < 4; i++)
#pragma unroll
                    for (int j = 0; j < 2; j++)
                        mma16816(acc[i][j], a[ta[e]][i], b[tb[e]][j]);
        }
        __syncthreads();
    }

    if (mode == 0){
        float* outp = Cp + (size_t)z * MPAD * HID;
#pragma unroll
        for (int i = 0; i < 4; i++){
            int mr = m0 + wm*64 + i*16 + (lane >> 2);
#pragma unroll
            for (int j = 0; j < 2; j++){
                int nc = n0 + wn*16 + j*8 + (lane & 3)*2;
                *(float2*)(outp + (size_t)mr*HID + nc) = make_float2(acc[i][j][0], acc[i][j][1]);
                *(float2*)(outp + (size_t)(mr+8)*HID + nc) = make_float2(acc[i][j][2], acc[i][j][3]);
            }
        }
    } else {
#pragma unroll
        for (int i = 0; i < 4; i++){
#pragma unroll
            for (int j = 0; j < 2; j++){
                int nc = n0 + wn*16 + j*8 + (lane & 3)*2;
#pragma unroll
                for (int h = 0; h < 2; h++){
                    int m = m0 + wm*64 + i*16 + (lane >> 2) + h*8;
                    if (m < NPROP){
                        if (nc < 105)   Oh[(size_t)m*105 + nc]   = acc[i][j][h*2]   + bias[nc];
                        if (nc+1 < 105) Oh[(size_t)m*105 + nc+1] = acc[i][j][h*2+1] + bias[nc+1];
                    }
                }
            }
        }
    }
}

// ---------------- sum split-K partials + bias + relu + split2 ----------------
__global__ void fixup_split(const float* __restrict__ p, const float* __restrict__ bias,
                            bf* __restrict__ o0, bf* __restrict__ o1){
    int i = blockIdx.x*256 + threadIdx.x;
    float v = fmaxf(p[i] + p[MPAD*HID + i] + bias[i & (HID-1)], 0.f);
    bf h0, h1; split2(v, h0, h1);
    o0[i] = h0; o1[i] = h1;
}

// ---------------- softmax + decode ----------------
__global__ void postproc_kernel(const float* __restrict__ rois){
    int m = blockIdx.x*128 + threadIdx.x;
    if (m >= NPROP) return;
    const float* h = g_head + (size_t)m*105;
    float lg[21], mx = -INFINITY;
#pragma unroll
    for (int c = 0; c < 21; c++){ lg[c] = h[c]; mx = fmaxf(mx, lg[c]); }
    float sum = 0.f;
#pragma unroll
    for (int c = 0; c < 21; c++){ lg[c] = expf(lg[c] - mx); sum += lg[c]; }
    float inv = 1.0f / sum;
    float4 r = ((const float4*)rois)[m];
    float w = r.z - r.x, hh = r.w - r.y;
    float cx = r.x + 0.5f*w, cy = r.y + 0.5f*hh;
#pragma unroll
    for (int c = 1; c < 21; c++){
        float sc = lg[c]*inv;
        float dx = h[21 + c*4 + 0], dy = h[21 + c*4 + 1];
        float dw = h[21 + c*4 + 2], dh = h[21 + c*4 + 3];
        float pcx = dx*w + cx, pcy = dy*hh + cy;
        float pw = expf(dw)*w, ph2 = expf(dh)*hh;
        float x1 = pcx - 0.5f*pw, y1 = pcy - 0.5f*ph2;
        float x2 = pcx + 0.5f*pw, y2 = pcy + 0.5f*ph2;
        int i = m*20 + (c - 1);
        g_boxes[i] = make_float4(x1, y1, x2, y2);
        float off = (float)c * 10000.0f;
        g_boxoff[i] = make_float4(x1 + off, y1 + off, x2 + off, y2 + off);
        g_cand[i] = sc;
    }
}

// ---------------- stable compaction (score > 0.05) ----------------
__global__ void compact_kernel(){
    __shared__ int woff[33];
    __shared__ int sbase;
    int t = threadIdx.x, w = t >> 5, l = t & 31;
    if (t == 0) sbase = 0;
    __syncthreads();
    for (int r = 0; r < NCAND; r += 1024){
        int i = r + t;
        float v = (i < NCAND) ? g_cand[i] : 0.f;
        bool p = (i < NCAND) && (v > 0.05f);
        unsigned bal = __ballot_sync(~0u, p);
        int pre = __popc(bal & ((1u << l) - 1));
        if (l == 0) woff[w] = __popc(bal);
        __syncthreads();
        if (t == 0){
            int s = sbase;
            for (int k = 0; k < 32; k++){ int x = woff[k]; woff[k] = s; s += x; }
            woff[32] = s;
            sbase = s;
        }
        __syncthreads();
        if (p){
            int d = woff[w] + pre;
            g_cscore[d] = v; g_cidx[d] = i;
            g_cboxoff[d] = g_boxoff[i]; g_cboxes[d] = g_boxes[i];
        }
        __syncthreads();
    }
    if (t == 0) g_ccount = sbase;
}

// ---------------- NMS on compacted set + early exit ----------------
__global__ void nms_kernel(float* __restrict__ out){
    extern __shared__ float s[];
    __shared__ float rv[32]; __shared__ int ri[32];
    __shared__ float4 pbS; __shared__ int s_stop, s_nd;
    __shared__ int keepI[MAXDET]; __shared__ float keepV[MAXDET];
    int t = threadIdx.x;
    int C = g_ccount;
    for (int i = t; i < C; i += 1024) s[i] = g_cscore[i];
    if (t == 0){ s_stop = 0; s_nd = 0; }
    __syncthreads();
    float4 pb = make_float4(0,0,0,0); float parea = 0.f; bool have = false;
    for (int it = 0; it < MAXDET; it++){
        float bv = -INFINITY; int bi = 1 << 30;
        for (int i = t; i < C; i += 1024){
            float v = s[i];
            if (have && v > -INFINITY){
                float4 b = g_cboxoff[i];
                float ix1 = fmaxf(pb.x, b.x), iy1 = fmaxf(pb.y, b.y);
                float ix2 = fminf(pb.z, b.z), iy2 = fminf(pb.w, b.w);
                float inter = fmaxf(ix2 - ix1, 0.f) * fmaxf(iy2 - iy1, 0.f);
                float A = (b.z - b.x) * (b.w - b.y);
                if (inter / (parea + A - inter + 1e-9f) > 0.5f){ v = -INFINITY; s[i] = v; }
            }
            if (v > bv || (v == bv && i < bi)){ bv = v; bi = i; }
        }
#pragma unroll
        for (int o = 16; o; o >>= 1){
            float ov = __shfl_down_sync(~0u, bv, o);
            int oi = __shfl_down_sync(~0u, bi, o);
            if (ov > bv || (ov == bv && oi < bi)){ bv = ov; bi = oi; }
        }
        if ((t & 31) == 0){ rv[t >> 5] = bv; ri[t >> 5] = bi; }
        __syncthreads();
        if (t < 32){
            bv = rv[t]; bi = ri[t];
#pragma unroll
            for (int o = 16; o; o >>= 1){
                float ov = __shfl_down_sync(~0u, bv, o);
                int oi = __shfl_down_sync(~0u, bi, o);
                if (ov > bv || (ov == bv && oi < bi)){ bv = ov; bi = oi; }
            }
            if (t == 0){
                if (bv > 0.05f){
                    keepI[s_nd] = bi; keepV[s_nd] = bv; s_nd++;
                    pbS = g_cboxoff[bi];
                } else s_stop = 1;
            }
        }
        __syncthreads();
        if (s_stop) break;
        pb = pbS; parea = (pb.z - pb.x) * (pb.w - pb.y); have = true;
        __syncthreads();
    }
    __syncthreads();
    if (t < s_nd){
        int ki = keepI[t];
        float4 b = g_cboxes[ki];
        out[t*4+0] = b.x; out[t*4+1] = b.y; out[t*4+2] = b.z; out[t*4+3] = b.w;
        out[400 + t] = keepV[t];
        out[500 + t] = (float)((g_cidx[ki] % 20) + 1);
    }
}

__global__ void zero_out(float* out, int n){
    int i = blockIdx.x*256 + threadIdx.x;
    if (i < n) out[i] = 0.f;
}

// ---------------- launcher ----------------
extern "C" void kernel_launch(void* const* d_in, const int* in_sizes, int n_in,
                              void* d_out, int out_size){
    const float* fm = (const float*)d_in[0];
    const float* pr = (const float*)d_in[1];
    const float* w1 = (const float*)d_in[2];
    const float* b1 = (const float*)d_in[3];
    const float* w2 = (const float*)d_in[4];
    const float* b2 = (const float*)d_in[5];
    const float* wc = (const float*)d_in[6];
    const float* bc = (const float*)d_in[7];
    const float* wb = (const float*)d_in[8];
    const float* bb = (const float*)d_in[9];
    float* out = (float*)d_out;

    bf *A0,*A1,*W10,*W11,*X1a,*X1b,*W20,*W21,*X2a,*X2b,*WH0,*WH1;
    float *bh, *head, *part;
    cudaGetSymbolAddress((void**)&A0, g_A0);   cudaGetSymbolAddress((void**)&A1, g_A1);
    cudaGetSymbolAddress((void**)&W10, g_W10); cudaGetSymbolAddress((void**)&W11, g_W11);
    cudaGetSymbolAddress((void**)&X1a, g_X1a); cudaGetSymbolAddress((void**)&X1b, g_X1b);
    cudaGetSymbolAddress((void**)&W20, g_W20); cudaGetSymbolAddress((void**)&W21, g_W21);
    cudaGetSymbolAddress((void**)&X2a, g_X2a); cudaGetSymbolAddress((void**)&X2b, g_X2b);
    cudaGetSymbolAddress((void**)&WH0, g_WH0); cudaGetSymbolAddress((void**)&WH1, g_WH1);
    cudaGetSymbolAddress((void**)&bh, g_bh);   cudaGetSymbolAddress((void**)&head, g_head);
    cudaGetSymbolAddress((void**)&part, g_part);

    cudaFuncSetAttribute(gemm_mma, cudaFuncAttributeMaxDynamicSharedMemorySize, GSMEM);
    cudaFuncSetAttribute(conv_pooled, cudaFuncAttributeMaxDynamicSharedMemorySize, 50372);
    cudaFuncSetAttribute(nms_kernel, cudaFuncAttributeMaxDynamicSharedMemorySize, NCAND*4);

    zero_out<<<(out_size + 255) / 256, 256>>>(out, out_size);
    transpose_fm<<<dim3(313, 8), dim3(32, 8)>>>(fm);
    roi_align_kernel<<<NPROP, 256>>>(pr);
    conv_pooled<<<MPAD, 256, 50372>>>();
    conv_T<<<dim3(32, 392), dim3(32, 8)>>>(w1, K1, HID, W10, W11);
    conv_T<<<dim3(32, 32), dim3(32, 8)>>>(w2, HID, HID, W20, W21);
    conv_heads<<<128, 256>>>(wc, bc, wb, bb);

    // FC1: [1024,12544] @ [12544,1024], split-K=2, BMxBN=128x128
    gemm_mma<<<dim3(8, 8, 2), 512, GSMEM>>>(A0, A1, W10, W11, nullptr, K1, 0, part, nullptr);
    fixup_split<<<MPAD*HID/256, 256>>>(part, b1, X1a, X1b);
    // FC2
    gemm_mma<<<dim3(8, 8, 2), 512, GSMEM>>>(X1a, X1b, W20, W21, nullptr, HID, 0, part, nullptr);
    fixup_split<<<MPAD*HID/256, 256>>>(part, b2, X2a, X2b);
    // heads: N=128 padded
    gemm_mma<<<dim3(1, 8, 1), 512, GSMEM>>>(X2a, X2b, WH0, WH1, bh, HID, 1, nullptr, head);

    postproc_kernel<<<8, 128>>>(pr);
    compact_kernel<<<1, 1024>>>();
    nms_kernel<<<1, 1024, NCAND*4>>>(out);
}